// round 12
// baseline (speedup 1.0000x reference)
#include <cuda_runtime.h>
#include <cuda_bf16.h>
#include <cuda_fp16.h>
#include <math.h>
#include <stdint.h>

#define BB    32
#define TT    8192
#define NTOK  (BB * TT)        // 262144
#define NJOB  (NTOK / 32)      // 8192 32-token jobs (2 mma tiles each)

// ---------------------------------------------------------------------------
// Device-global scratch
// ---------------------------------------------------------------------------
// Per-vocab tables, row 500 = zeros (causal pad). b1 folded into T2b/T3c.
__device__ float g_T2a[501 * 256];
__device__ float g_T2b[501 * 256];
__device__ float g_T3a[501 * 256];
__device__ float g_T3b[501 * 256];
__device__ float g_T3c[501 * 256];
__device__ float  g_Val [(size_t)NTOK * 64];
__device__ __half g_ValN[(size_t)NTOK * 64];
// Fused fragment images: per mma-tile, per lane, uint4 {hi0, hi1, lo0, lo1}.
// G1: tiles 0..127 @ 0; G2: @ 4096 uint4; G3: @ 8192 uint4.
// G1/G2 use the k-permuted layout (A loads its own float4); G3 is standard.
__device__ uint4 g_Bimg[12288];
// kv bias with emb-bias folded: kvb[n] = b2cat @ KVW[:,n] + (keyb|valb)[n]
__device__ float g_kvb[128];

__device__ __forceinline__ float silu_f(float x) {
    return __fdividef(x, 1.0f + __expf(-x));
}
__device__ __forceinline__ float qsum(float v) {   // sum over quad (4 lanes)
    v += __shfl_xor_sync(0xffffffffu, v, 1);
    v += __shfl_xor_sync(0xffffffffu, v, 2);
    return v;
}
// hi/lo bf16 split of a float pair -> packed bf16x2 regs
__device__ __forceinline__ void split2(float a, float b, uint32_t& hi, uint32_t& lo) {
    __nv_bfloat162 h = __floats2bfloat162_rn(a, b);
    __nv_bfloat162 l = __floats2bfloat162_rn(a - __low2float(h), b - __high2float(h));
    hi = *(uint32_t*)&h;
    lo = *(uint32_t*)&l;
}
__device__ __forceinline__ void mma16816(float* d, const uint32_t* a,
                                         uint32_t b0, uint32_t b1) {
    asm volatile(
        "mma.sync.aligned.m16n8k16.row.col.f32.bf16.bf16.f32 "
        "{%0,%1,%2,%3}, {%4,%5,%6,%7}, {%8,%9}, {%0,%1,%2,%3};"
        : "+f"(d[0]), "+f"(d[1]), "+f"(d[2]), "+f"(d[3])
        : "r"(a[0]), "r"(a[1]), "r"(a[2]), "r"(a[3]), "r"(b0), "r"(b1));
}

// GEMM3 quarter: consume one D-half S (8 n-tiles) as A for k-tiles [ktoff,ktoff+4)
__device__ __forceinline__ void gemm3_quarter(float* DK, const float* S,
                                              const uint4* Bs4, int lane,
                                              int ktoff) {
#pragma unroll
    for (int kt = 0; kt < 4; kt++) {
        const int tb = kt * 2;
        uint32_t ah[4], al[4];
        split2(S[tb*4+0], S[tb*4+1], ah[0], al[0]);
        split2(S[tb*4+2], S[tb*4+3], ah[1], al[1]);
        split2(S[tb*4+4], S[tb*4+5], ah[2], al[2]);
        split2(S[tb*4+6], S[tb*4+7], ah[3], al[3]);
#pragma unroll
        for (int nt = 0; nt < 16; nt++) {
            const uint4 q = Bs4[8192 + ((ktoff + kt) * 16 + nt) * 32 + lane];
            mma16816(DK + nt*4, ah, q.x, q.y);
            mma16816(DK + nt*4, al, q.x, q.y);
            mma16816(DK + nt*4, ah, q.z, q.w);
        }
    }
}

// Epilogue for one m16 tile: LN(k), LN(hidden), gate, value, conv-LN.
__device__ __forceinline__ void epilogue(
    const float* DK, int tbase, int r, int qc,
    const float* __restrict__ hidden,
    const float* __restrict__ n1g, const float* __restrict__ n1b,
    const float* __restrict__ n2g, const float* __restrict__ n2b,
    const float* __restrict__ cg,  const float* __restrict__ cb) {
#pragma unroll
    for (int h = 0; h < 2; h++) {
        const int t = tbase + r + 8 * h;
        float kd[16], s = 0.f, q = 0.f;
#pragma unroll
        for (int nt = 0; nt < 8; nt++) {
            const float2 kb = *(const float2*)(g_kvb + nt*8 + qc);
            const float u0 = DK[nt*4 + 2*h]     + kb.x;
            const float u1 = DK[nt*4 + 2*h + 1] + kb.y;
            kd[nt*2] = u0; kd[nt*2+1] = u1;
            s += u0 + u1;  q += u0*u0 + u1*u1;
        }
        s = qsum(s); q = qsum(q);
        const float mk = s * (1.f/64.f);
        const float ik = rsqrtf(q * (1.f/64.f) - mk*mk + 1e-5f);
        float hv[16], hs = 0.f, hq = 0.f;
#pragma unroll
        for (int nt = 0; nt < 8; nt++) {
            const float2 hh = *(const float2*)(hidden + (size_t)t*64 + nt*8 + qc);
            hv[nt*2] = hh.x; hv[nt*2+1] = hh.y;
            hs += hh.x + hh.y;  hq += hh.x*hh.x + hh.y*hh.y;
        }
        hs = qsum(hs); hq = qsum(hq);
        const float mh = hs * (1.f/64.f);
        const float ih = rsqrtf(hq * (1.f/64.f) - mh*mh + 1e-5f);
        float dp = 0.f;
#pragma unroll
        for (int nt = 0; nt < 8; nt++) {
            const int col = nt*8 + qc;
            const float2 ga = *(const float2*)(n1g + col);
            const float2 ba = *(const float2*)(n1b + col);
            const float2 gb = *(const float2*)(n2g + col);
            const float2 bbv = *(const float2*)(n2b + col);
            const float nk0 = (kd[nt*2]   - mk) * ik * ga.x + ba.x;
            const float nk1 = (kd[nt*2+1] - mk) * ik * ga.y + ba.y;
            const float nq0 = (hv[nt*2]   - mh) * ih * gb.x + bbv.x;
            const float nq1 = (hv[nt*2+1] - mh) * ih * gb.y + bbv.y;
            dp += nk0*nq0 + nk1*nq1;
        }
        dp = qsum(dp) * 0.125f;
        const float sq = sqrtf(fmaxf(fabsf(dp), 1e-6f));
        const float gs = (dp > 0.f) ? sq : ((dp < 0.f) ? -sq : 0.f);
        const float gate = __fdividef(1.f, 1.f + __expf(-gs));
        float gv[16], vs = 0.f, vq = 0.f;
#pragma unroll
        for (int nt = 8; nt < 16; nt++) {
            const float2 kb = *(const float2*)(g_kvb + nt*8 + qc);
            const float g0 = gate * (DK[nt*4 + 2*h]     + kb.x);
            const float g1 = gate * (DK[nt*4 + 2*h + 1] + kb.y);
            gv[(nt-8)*2] = g0; gv[(nt-8)*2+1] = g1;
            *(float2*)(g_Val + (size_t)t*64 + (nt-8)*8 + qc) = make_float2(g0, g1);
            vs += g0 + g1;  vq += g0*g0 + g1*g1;
        }
        vs = qsum(vs); vq = qsum(vq);
        const float mv = vs * (1.f/64.f);
        const float iv = rsqrtf(vq * (1.f/64.f) - mv*mv + 1e-5f);
#pragma unroll
        for (int nt = 0; nt < 8; nt++) {
            const int col = nt*8 + qc;
            const float2 gc = *(const float2*)(cg + col);
            const float2 bc = *(const float2*)(cb + col);
            const float v0 = (gv[nt*2]   - mv) * iv * gc.x + bc.x;
            const float v1 = (gv[nt*2+1] - mv) * iv * gc.y + bc.y;
            *(__half2*)(g_ValN + (size_t)t*64 + col) = __floats2half2_rn(v0, v1);
        }
    }
}

// ---------------------------------------------------------------------------
// Kernel 1 (merged prep): blocks 0..500 build per-vocab tables (row 500 = 0);
// blocks 501..548 build fused-fragment B images; block 501 also folds kv bias.
// ---------------------------------------------------------------------------
__global__ void prep_kernel(const float* __restrict__ emb,
                            const float* __restrict__ W1_2,
                            const float* __restrict__ b1_2,
                            const float* __restrict__ W1_3,
                            const float* __restrict__ b1_3,
                            const float* __restrict__ W2_2,
                            const float* __restrict__ W2_3,
                            const float* __restrict__ keyW,
                            const float* __restrict__ valW,
                            const float* __restrict__ b2_2,
                            const float* __restrict__ b2_3,
                            const float* __restrict__ keyb,
                            const float* __restrict__ valb) {
    if (blockIdx.x <= 500) {
        __shared__ float e[64];
        const int id = blockIdx.x, o = threadIdx.x;
        if (id == 500) {
            g_T2a[id*256+o] = 0.f; g_T2b[id*256+o] = 0.f;
            g_T3a[id*256+o] = 0.f; g_T3b[id*256+o] = 0.f; g_T3c[id*256+o] = 0.f;
            return;
        }
        if (o < 64) e[o] = emb[id * 64 + o];
        __syncthreads();
        float a2=0.f, b2=0.f, a3=0.f, b3=0.f, c3=0.f;
#pragma unroll 8
        for (int d = 0; d < 64; d++) {
            const float ev = e[d];
            a2 += ev * W1_2[d*256 + o];
            b2 += ev * W1_2[(64+d)*256 + o];
            a3 += ev * W1_3[d*256 + o];
            b3 += ev * W1_3[(64+d)*256 + o];
            c3 += ev * W1_3[(128+d)*256 + o];
        }
        g_T2a[id*256+o] = a2;  g_T2b[id*256+o] = b2 + b1_2[o];
        g_T3a[id*256+o] = a3;  g_T3b[id*256+o] = b3;
        g_T3c[id*256+o] = c3 + b1_3[o];
        return;
    }

    const int idx = (blockIdx.x - 501) * blockDim.x + threadIdx.x;
    if (idx < 12288) {
        const int g    = idx >> 12;
        const int tile = (idx >> 5) & 127;
        const int lane = idx & 31;
        const int NT = (g == 2) ? 16 : 8;
        const int kt = tile / NT, nt = tile % NT;
        const int n  = nt*8 + (lane >> 2);
        int ka, kb, kc, kd;
        if (g < 2) {   // k-permuted: contiguous quad feeds A-fragment float4
            const int k0 = kt*16 + (lane & 3)*4;
            ka = k0; kb = k0+1; kc = k0+2; kd = k0+3;
        } else {       // standard mma B layout
            const int k0 = kt*16 + (lane & 3)*2;
            ka = k0; kb = k0+1; kc = k0+8; kd = k0+9;
        }
        float w00, w01, w10, w11;
        if (g == 0) {
            w00 = W2_2[ka*64+n]; w01 = W2_2[kb*64+n];
            w10 = W2_2[kc*64+n]; w11 = W2_2[kd*64+n];
        } else if (g == 1) {
            w00 = W2_3[ka*64+n]; w01 = W2_3[kb*64+n];
            w10 = W2_3[kc*64+n]; w11 = W2_3[kd*64+n];
        } else if (n < 64) {
            w00 = keyW[ka*64+n]; w01 = keyW[kb*64+n];
            w10 = keyW[kc*64+n]; w11 = keyW[kd*64+n];
        } else {
            w00 = valW[ka*64+n-64]; w01 = valW[kb*64+n-64];
            w10 = valW[kc*64+n-64]; w11 = valW[kd*64+n-64];
        }
        uint4 q;
        split2(w00, w01, q.x, q.z);
        split2(w10, w11, q.y, q.w);
        g_Bimg[idx] = q;
    }
    if (blockIdx.x == 501 && threadIdx.x < 128) {
        const int nn = threadIdx.x;
        float s = (nn < 64) ? keyb[nn] : valb[nn - 64];
        for (int jj = 0; jj < 128; jj++) {
            const float bj = (jj < 64) ? b2_2[jj] : b2_3[jj - 64];
            const float w  = (nn < 64) ? keyW[jj*64 + nn] : valW[jj*64 + nn - 64];
            s += bj * w;
        }
        g_kvb[nn] = s;
    }
}

// ---------------------------------------------------------------------------
// Kernel 2: main fused kernel. 148 CTAs x 256 thr (8 warps); warp = 32 tokens
// (two m16 tiles, B fragments amortized across the pair in GEMM1/GEMM2).
// ---------------------------------------------------------------------------
__global__ void __launch_bounds__(256, 1)
main_kernel(const int*   __restrict__ ids,
            const float* __restrict__ hidden,
            const float* __restrict__ n1g, const float* __restrict__ n1b,
            const float* __restrict__ n2g, const float* __restrict__ n2b,
            const float* __restrict__ cg,  const float* __restrict__ cb) {
    extern __shared__ uint4 Bs4[];   // 12288 uint4 = 192 KB
    for (int i = threadIdx.x; i < 12288; i += 256) Bs4[i] = g_Bimg[i];
    __syncthreads();

    const int wid  = threadIdx.x >> 5;
    const int lane = threadIdx.x & 31;
    const int r    = lane >> 2;          // fragment row (0..7)
    const int qc   = (lane & 3) * 2;     // fragment col base (0,2,4,6)
    const int qq   = (lane & 3) * 4;     // permuted-gather col base (0,4,8,12)
    const int gw   = blockIdx.x * 8 + wid;

    for (int job = gw; job < NJOB; job += 148 * 8) {
        const int t0 = job * 32;
        const int p0 = t0 & 8191;        // job never crosses batch boundary

        // uh = u*2 + h -> token offset uh*8 + r
        int ic[4], i1[4], i2[4];
#pragma unroll
        for (int uh = 0; uh < 4; uh++) {
            const int off = uh * 8 + r;
            const int pp = p0 + off;
            ic[uh] = ids[t0 + off];
            i1[uh] = (pp >= 1) ? ids[t0 + off - 1] : 500;
            i2[uh] = (pp >= 2) ? ids[t0 + off - 2] : 500;
        }

        float DK0[64], DK1[64];
#pragma unroll
        for (int i = 0; i < 64; i++) { DK0[i] = 0.f; DK1[i] = 0.f; }

        // ========== phase A: GEMM1 (both tiles, B amortized) ==========
        {
            float D10[32], D11[32];
#pragma unroll
            for (int i = 0; i < 32; i++) { D10[i] = 0.f; D11[i] = 0.f; }
            for (int kt = 0; kt < 16; kt++) {
                uint32_t ah0[4], al0[4], ah1[4], al1[4];
                const int cbs = kt * 16 + qq;
#pragma unroll
                for (int h = 0; h < 2; h++) {
                    {
                        const float4 x = *(const float4*)(g_T2b + ic[h] * 256 + cbs);
                        const float4 y = *(const float4*)(g_T2a + i1[h] * 256 + cbs);
                        split2(silu_f(x.x + y.x), silu_f(x.y + y.y), ah0[h],   al0[h]);
                        split2(silu_f(x.z + y.z), silu_f(x.w + y.w), ah0[h+2], al0[h+2]);
                    }
                    {
                        const float4 x = *(const float4*)(g_T2b + ic[2+h] * 256 + cbs);
                        const float4 y = *(const float4*)(g_T2a + i1[2+h] * 256 + cbs);
                        split2(silu_f(x.x + y.x), silu_f(x.y + y.y), ah1[h],   al1[h]);
                        split2(silu_f(x.z + y.z), silu_f(x.w + y.w), ah1[h+2], al1[h+2]);
                    }
                }
#pragma unroll
                for (int nt = 0; nt < 8; nt++) {
                    const uint4 q = Bs4[(kt * 8 + nt) * 32 + lane];
                    mma16816(D10 + nt*4, ah0, q.x, q.y);
                    mma16816(D10 + nt*4, al0, q.x, q.y);
                    mma16816(D10 + nt*4, ah0, q.z, q.w);
                    mma16816(D11 + nt*4, ah1, q.x, q.y);
                    mma16816(D11 + nt*4, al1, q.x, q.y);
                    mma16816(D11 + nt*4, ah1, q.z, q.w);
                }
            }
            gemm3_quarter(DK0, D10, Bs4, lane, 0);
            gemm3_quarter(DK1, D11, Bs4, lane, 0);
        }

        // ========== phase B: GEMM2 (both tiles, B amortized) ==========
        {
            float D20[32], D21[32];
#pragma unroll
            for (int i = 0; i < 32; i++) { D20[i] = 0.f; D21[i] = 0.f; }
            for (int kt = 0; kt < 16; kt++) {
                uint32_t ah0[4], al0[4], ah1[4], al1[4];
                const int cbs = kt * 16 + qq;
#pragma unroll
                for (int h = 0; h < 2; h++) {
                    {
                        const float4 x = *(const float4*)(g_T3c + ic[h] * 256 + cbs);
                        const float4 y = *(const float4*)(g_T3b + i1[h] * 256 + cbs);
                        const float4 z = *(const float4*)(g_T3a + i2[h] * 256 + cbs);
                        split2(silu_f(x.x + y.x + z.x), silu_f(x.y + y.y + z.y),
                               ah0[h],   al0[h]);
                        split2(silu_f(x.z + y.z + z.z), silu_f(x.w + y.w + z.w),
                               ah0[h+2], al0[h+2]);
                    }
                    {
                        const float4 x = *(const float4*)(g_T3c + ic[2+h] * 256 + cbs);
                        const float4 y = *(const float4*)(g_T3b + i1[2+h] * 256 + cbs);
                        const float4 z = *(const float4*)(g_T3a + i2[2+h] * 256 + cbs);
                        split2(silu_f(x.x + y.x + z.x), silu_f(x.y + y.y + z.y),
                               ah1[h],   al1[h]);
                        split2(silu_f(x.z + y.z + z.z), silu_f(x.w + y.w + z.w),
                               ah1[h+2], al1[h+2]);
                    }
                }
#pragma unroll
                for (int nt = 0; nt < 8; nt++) {
                    const uint4 q = Bs4[4096 + (kt * 8 + nt) * 32 + lane];
                    mma16816(D20 + nt*4, ah0, q.x, q.y);
                    mma16816(D20 + nt*4, al0, q.x, q.y);
                    mma16816(D20 + nt*4, ah0, q.z, q.w);
                    mma16816(D21 + nt*4, ah1, q.x, q.y);
                    mma16816(D21 + nt*4, al1, q.x, q.y);
                    mma16816(D21 + nt*4, ah1, q.z, q.w);
                }
            }
            gemm3_quarter(DK0, D20, Bs4, lane, 4);
            gemm3_quarter(DK1, D21, Bs4, lane, 4);
        }

        // ========== epilogue: tile u=0 then u=1 ==========
        epilogue(DK0, t0,      r, qc, hidden, n1g, n1b, n2g, n2b, cg, cb);
        epilogue(DK1, t0 + 16, r, qc, hidden, n1g, n1b, n2g, n2b, cg, cb);
    }
}

// ---------------------------------------------------------------------------
// Kernel 3: streaming causal dilated depthwise conv (fp16 LN'd taps).
// Warp per token, 2 dims per thread (fastest measured shape).
// ---------------------------------------------------------------------------
__global__ void conv_kernel(const float* __restrict__ cw,
                            float* __restrict__ out) {
    const int g     = blockIdx.x * blockDim.x + threadIdx.x;
    const int token = g >> 5;
    const int d0    = (g & 31) * 2;
    const int p     = token & 8191;

    const float4 w0 = *(const float4*)(cw + d0 * 4);
    const float4 w1 = *(const float4*)(cw + d0 * 4 + 4);

    float y0 = 0.f, y1 = 0.f;
    const __half* basen = g_ValN + (size_t)token * 64 + d0;
#pragma unroll
    for (int j = 0; j < 4; j++) {
        const int tp = p - 9 + 3 * j;
        if (tp >= 0) {
            const __half2 vh = *(const __half2*)(basen + (long)(3 * j - 9) * 64);
            const float2 v = __half22float2(vh);
            y0 += ((const float*)&w0)[j] * v.x;
            y1 += ((const float*)&w1)[j] * v.y;
        }
    }
    const float2 rr = __ldcs((const float2*)(g_Val + (size_t)token * 64 + d0));
    __stcs((float2*)(out + (size_t)token * 64 + d0),
           make_float2(rr.x + silu_f(y0), rr.y + silu_f(y1)));
}

// ---------------------------------------------------------------------------
// Host launcher
// ---------------------------------------------------------------------------
extern "C" void kernel_launch(void* const* d_in, const int* in_sizes, int n_in,
                              void* d_out, int out_size) {
    const float* hidden = (const float*)d_in[0];
    const int*   ids    = (const int*)d_in[1];
    const float* emb    = (const float*)d_in[2];
    const float* W1_2   = (const float*)d_in[3];
    const float* b1_2   = (const float*)d_in[4];
    const float* W2_2   = (const float*)d_in[5];
    const float* b2_2   = (const float*)d_in[6];
    const float* W1_3   = (const float*)d_in[7];
    const float* b1_3   = (const float*)d_in[8];
    const float* W2_3   = (const float*)d_in[9];
    const float* b2_3   = (const float*)d_in[10];
    const float* keyW   = (const float*)d_in[11];
    const float* keyb   = (const float*)d_in[12];
    const float* valW   = (const float*)d_in[13];
    const float* valb   = (const float*)d_in[14];
    const float* n1g    = (const float*)d_in[15];
    const float* n1b    = (const float*)d_in[16];
    const float* n2g    = (const float*)d_in[17];
    const float* n2b    = (const float*)d_in[18];
    const float* cw     = (const float*)d_in[19];
    const float* cg     = (const float*)d_in[20];
    const float* cb     = (const float*)d_in[21];
    float* out = (float*)d_out;

    prep_kernel<<<549, 256>>>(emb, W1_2, b1_2, W1_3, b1_3,
                              W2_2, W2_3, keyW, valW,
                              b2_2, b2_3, keyb, valb);

    const size_t smem = 12288 * sizeof(uint4);  // 196608 B
    cudaFuncSetAttribute(main_kernel, cudaFuncAttributeMaxDynamicSharedMemorySize,
                         (int)smem);
    main_kernel<<<148, 256, smem>>>(ids, hidden, n1g, n1b, n2g, n2b, cg, cb);

    conv_kernel<<<NTOK * 32 / 256, 256>>>(cw, out);
}